// round 15
// baseline (speedup 1.0000x reference)
#include <cuda_runtime.h>

#define NB   256   // batch
#define HD   1024  // hidden
#define NOBS 256   // obs dim
#define NA   18    // actions
#define SPLIT 4

// Scratch (allocation-free rule: __device__ globals).
__device__ float g_part[SPLIT * NB * HD];   // split-K partials (4 MB)
__device__ float g_h1[NB * HD];
__device__ float g_h2[NB * HD];
__device__ float g_h3[NB * HD];

enum { M_FMA = 0, M_MAX = 1, M_MIN = 2 };

constexpr int BT = 64;        // batch tile (8 b per thread)
constexpr int OT = 128;       // out tile (4 o per thread)
constexpr int KC = 32;        // k chunk
constexpr int NT = 256;       // threads (8 warps)
constexpr int WST = 132;      // OT+4
constexpr int HST = 68;       // BT+4
constexpr int SW_SZ = KC * WST;
constexpr int SH_SZ = KC * HST;
constexpr int SMEM_BYTES = 2 * (SW_SZ + SH_SZ) * 4;  // 51200 B dynamic

// out[b,o] = red_i op(W[o,i], h[b,i]) over i in [i0, i0+Ki); partial per z.
// Double-buffered smem, one barrier per chunk, per-thread tile 8b x 4o.
// Loader mapping: warp = i4-slot, lane = column -> conflict-free STS
// (bank = lane + 4*row mod 32, all 32 lanes distinct per store step).
template<int MODE>
__global__ __launch_bounds__(NT, 2)
void semiring_kernel(const float* __restrict__ Wm, const float* __restrict__ Hin,
                     float* __restrict__ part, int Kld, int Ki)
{
    extern __shared__ float smem[];
    float* sw = smem;                 // [2][KC][WST]  sw[i][o]
    float* sh = smem + 2 * SW_SZ;     // [2][KC][HST]  sh[i][b]

    const int tid = threadIdx.x;
    const int o0  = blockIdx.x * OT;
    const int b0  = blockIdx.y * BT;
    const int i0  = blockIdx.z * Ki;

    const int og = tid & 31;   // compute: o = o0 + og*4 + oo
    const int bg = tid >> 5;   // compute: b = b0 + bg*8 + bb
    const int iw = tid >> 5;   // loader: warp -> i4 slot (0..7)
    const int ln = tid & 31;   // loader: lane -> column

    const float init = (MODE == M_FMA) ? 0.0f
                     : (MODE == M_MAX) ? -3.402823466e38f : 3.402823466e38f;
    float acc[8][4];
#pragma unroll
    for (int bb = 0; bb < 8; bb++)
#pragma unroll
        for (int oo = 0; oo < 4; oo++) acc[bb][oo] = init;

    const float* wb = Wm  + (o0 + ln) * Kld + i0 + iw * 4;  // cols ln,+32,+64,+96
    const float* hb = Hin + (b0 + ln) * Kld + i0 + iw * 4;  // cols ln,+32

    float4 wreg[4], hreg[2];
    const int nC = Ki / KC;

    // ---- prologue: chunk 0 -> regs -> buf 0 ----
#pragma unroll
    for (int r = 0; r < 4; r++) wreg[r] = *(const float4*)(wb + r * 32 * Kld);
#pragma unroll
    for (int rr = 0; rr < 2; rr++) hreg[rr] = *(const float4*)(hb + rr * 32 * Kld);
    {
        const int row0 = iw * 4;
#pragma unroll
        for (int r = 0; r < 4; r++) {
            const float wv[4] = {wreg[r].x, wreg[r].y, wreg[r].z, wreg[r].w};
#pragma unroll
            for (int k = 0; k < 4; k++)
                sw[(row0 + k) * WST + ln + r * 32] = wv[k];   // conflict-free
        }
#pragma unroll
        for (int rr = 0; rr < 2; rr++) {
            const float hv[4] = {hreg[rr].x, hreg[rr].y, hreg[rr].z, hreg[rr].w};
#pragma unroll
            for (int k = 0; k < 4; k++)
                sh[(row0 + k) * HST + ln + rr * 32] = hv[k];  // conflict-free
        }
    }
    __syncthreads();

    for (int c = 0; c < nC; c++) {
        // prefetch chunk c+1 into regs (overlaps with compute)
        if (c + 1 < nC) {
            const int ic = (c + 1) * KC;
#pragma unroll
            for (int r = 0; r < 4; r++)
                wreg[r] = *(const float4*)(wb + r * 32 * Kld + ic);
#pragma unroll
            for (int rr = 0; rr < 2; rr++)
                hreg[rr] = *(const float4*)(hb + rr * 32 * Kld + ic);
        }

        const float* pw = sw + (c & 1) * SW_SZ;
        const float* ph = sh + (c & 1) * SH_SZ;
#pragma unroll 4
        for (int i = 0; i < KC; i++) {
            const float4 wv = *(const float4*)&pw[i * WST + og * 4];
            const float4 h0 = *(const float4*)&ph[i * HST + bg * 8];
            const float4 h1 = *(const float4*)&ph[i * HST + bg * 8 + 4];
            const float w4[4] = {wv.x, wv.y, wv.z, wv.w};
            const float h8[8] = {h0.x, h0.y, h0.z, h0.w, h1.x, h1.y, h1.z, h1.w};
#pragma unroll
            for (int bb = 0; bb < 8; bb++)
#pragma unroll
                for (int oo = 0; oo < 4; oo++) {
                    if (MODE == M_FMA)
                        acc[bb][oo] = fmaf(w4[oo], h8[bb], acc[bb][oo]);
                    else if (MODE == M_MAX)
                        acc[bb][oo] = fmaxf(acc[bb][oo], w4[oo] + h8[bb]);
                    else
                        acc[bb][oo] = fminf(acc[bb][oo], w4[oo] + h8[bb]);
                }
        }

        // stage chunk c+1 into the other buffer; single barrier per chunk
        if (c + 1 < nC) {
            float* qw = sw + ((c + 1) & 1) * SW_SZ;
            float* qh = sh + ((c + 1) & 1) * SH_SZ;
            const int row0 = iw * 4;
#pragma unroll
            for (int r = 0; r < 4; r++) {
                const float wv[4] = {wreg[r].x, wreg[r].y, wreg[r].z, wreg[r].w};
#pragma unroll
                for (int k = 0; k < 4; k++)
                    qw[(row0 + k) * WST + ln + r * 32] = wv[k];
            }
#pragma unroll
            for (int rr = 0; rr < 2; rr++) {
                const float hv[4] = {hreg[rr].x, hreg[rr].y, hreg[rr].z, hreg[rr].w};
#pragma unroll
                for (int k = 0; k < 4; k++)
                    qh[(row0 + k) * HST + ln + rr * 32] = hv[k];
            }
            __syncthreads();
        }
    }

    float* pout = part + (blockIdx.z * NB + b0 + bg * 8) * HD + o0 + og * 4;
#pragma unroll
    for (int bb = 0; bb < 8; bb++)
        *(float4*)(pout + bb * HD) =
            make_float4(acc[bb][0], acc[bb][1], acc[bb][2], acc[bb][3]);
}

// Reduce SPLIT partials -> dense activation (one thread per output float4,
// MLP=4 independent loads). base allows splitting one combine across launches.
template<int MODE>
__global__ __launch_bounds__(256)
void combine_kernel(const float* __restrict__ part, float* __restrict__ out,
                    const float* __restrict__ bias, int base)
{
    const int idx = base + blockIdx.x * 256 + threadIdx.x;  // float4 index
    const float4* p = (const float4*)part + idx;
    float4 v = p[0];
#pragma unroll
    for (int s = 1; s < SPLIT; s++) {
        const float4 u = p[s * (NB * HD / 4)];
        if (MODE == M_FMA) {
            v.x += u.x; v.y += u.y; v.z += u.z; v.w += u.w;
        } else if (MODE == M_MAX) {
            v.x = fmaxf(v.x, u.x); v.y = fmaxf(v.y, u.y);
            v.z = fmaxf(v.z, u.z); v.w = fmaxf(v.w, u.w);
        } else {
            v.x = fminf(v.x, u.x); v.y = fminf(v.y, u.y);
            v.z = fminf(v.z, u.z); v.w = fminf(v.w, u.w);
        }
    }
    if (MODE == M_FMA) {
        const float4 b = *(const float4*)(bias + (idx & (HD / 4 - 1)) * 4);
        v.x += b.x; v.y += b.y; v.z += b.z; v.w += b.w;
    }
    ((float4*)out)[idx] = v;
}

// One CTA per batch row b: stage dense h3 row into smem, 8 warps x 18 dots.
__global__ __launch_bounds__(256)
void fcout_kernel(const float* __restrict__ h3, const float* __restrict__ Wout,
                  const float* __restrict__ bout, float* __restrict__ q)
{
    __shared__ float sh[HD];
    const int b    = blockIdx.x;
    const int tid  = threadIdx.x;
    const int wid  = tid >> 5;
    const int lane = tid & 31;

    ((float4*)sh)[tid] = ((const float4*)h3)[b * (HD / 4) + tid];
    __syncthreads();

    for (int a = wid; a < NA; a += 8) {
        const float4* wr = (const float4*)(Wout + a * HD);
        const float4* hs = (const float4*)sh;
        float s = 0.0f;
#pragma unroll
        for (int k = 0; k < HD / 128; k++) {
            const float4 w4 = wr[lane + k * 32];
            const float4 h4 = hs[lane + k * 32];
            s = fmaf(w4.x, h4.x, s);
            s = fmaf(w4.y, h4.y, s);
            s = fmaf(w4.z, h4.z, s);
            s = fmaf(w4.w, h4.w, s);
        }
#pragma unroll
        for (int d = 16; d; d >>= 1) s += __shfl_xor_sync(0xffffffffu, s, d);
        if (lane == 0) q[b * NA + a] = s + bout[a];
    }
}

extern "C" void kernel_launch(void* const* d_in, const int* in_sizes, int n_in,
                              void* d_out, int out_size)
{
    const float* x     = (const float*)d_in[0];
    const float* W_in  = (const float*)d_in[1];
    const float* b_in  = (const float*)d_in[2];
    const float* W_max = (const float*)d_in[3];
    const float* W_min = (const float*)d_in[4];
    const float* W_out = (const float*)d_in[5];
    const float* b_out = (const float*)d_in[6];
    float* q = (float*)d_out;

    float *part, *h1, *h2, *h3;
    cudaGetSymbolAddress((void**)&part, g_part);
    cudaGetSymbolAddress((void**)&h1, g_h1);
    cudaGetSymbolAddress((void**)&h2, g_h2);
    cudaGetSymbolAddress((void**)&h3, g_h3);

    cudaFuncSetAttribute(semiring_kernel<M_FMA>,
                         cudaFuncAttributeMaxDynamicSharedMemorySize, SMEM_BYTES);
    cudaFuncSetAttribute(semiring_kernel<M_MAX>,
                         cudaFuncAttributeMaxDynamicSharedMemorySize, SMEM_BYTES);
    cudaFuncSetAttribute(semiring_kernel<M_MIN>,
                         cudaFuncAttributeMaxDynamicSharedMemorySize, SMEM_BYTES);

    const dim3 grid(HD / OT, NB / BT, SPLIT);   // (8, 4, 4) = 128 CTAs, 1/SM
    const int  N4 = NB * HD / 4;                // 65536 float4 outputs

    // 0) fc_in partials
    semiring_kernel<M_FMA><<<grid, NT, SMEM_BYTES>>>(W_in, x, part, NOBS, NOBS / SPLIT);
    // 1,2) combine(sum,+b_in) -> h1, split in two so launch #3 is a semiring
    combine_kernel<M_FMA><<<N4 / 2 / 256, 256>>>(part, h1, b_in, 0);
    combine_kernel<M_FMA><<<N4 / 2 / 256, 256>>>(part, h1, b_in, N4 / 2);

    // 3) max-plus partials  (ncu capture lands HERE)
    semiring_kernel<M_MAX><<<grid, NT, SMEM_BYTES>>>(W_max, h1, part, HD, HD / SPLIT);
    // 4) combine(max) -> h2
    combine_kernel<M_MAX><<<N4 / 256, 256>>>(part, h2, nullptr, 0);

    // 5) min-plus partials
    semiring_kernel<M_MIN><<<grid, NT, SMEM_BYTES>>>(W_min, h2, part, HD, HD / SPLIT);
    // 6) combine(min) -> h3
    combine_kernel<M_MIN><<<N4 / 256, 256>>>(part, h3, nullptr, 0);

    // 7) fc_out
    fcout_kernel<<<NB, 256>>>(h3, W_out, b_out, q);
}

// round 17
// speedup vs baseline: 1.0846x; 1.0846x over previous
#include <cuda_runtime.h>

#define NB   256   // batch
#define HD   1024  // hidden
#define NOBS 256   // obs dim
#define NA   18    // actions
#define SPLIT 8

// Scratch (allocation-free rule: __device__ globals).
__device__ float g_part[SPLIT * NB * HD];   // split-K partials (8 MB)
__device__ float g_h1[NB * HD];
__device__ float g_h2[NB * HD];
__device__ float g_h3[NB * HD];

enum { M_FMA = 0, M_MAX = 1, M_MIN = 2 };

constexpr int BT = 64;        // batch tile (8 b per thread)
constexpr int OT = 128;       // out tile (4 o per thread)
constexpr int KC = 32;        // k chunk
constexpr int NT = 256;       // threads (8 warps)
constexpr int WST = 132;      // OT+4
constexpr int HST = 68;       // BT+4
constexpr int SW_SZ = KC * WST;
constexpr int SH_SZ = KC * HST;
constexpr int SMEM_BYTES = 2 * (SW_SZ + SH_SZ) * 4;  // 51200 B dynamic; 2 CTAs/SM = 100 KB

template<int MODE>
__device__ __forceinline__ float red(float a, float w, float h)
{
    if (MODE == M_FMA) return fmaf(w, h, a);
    if (MODE == M_MAX) return fmaxf(a, w + h);
    return fminf(a, w + h);
}

// out[b,o] = red_i op(W[o,i], h[b,i]) over i in [i0, i0+Ki); partial per z.
// Grid 256 CTAs @ 2 CTAs/SM (16 warps/SM): R15 profile showed 8 warps/SM is
// stall-bound (issue 63.7%, both pipes <45%). Coalesced R11 loader (4-line
// LDG.128); double-buffered smem, one barrier per chunk; 8b x 4o per thread.
template<int MODE>
__global__ __launch_bounds__(NT, 2)
void semiring_kernel(const float* __restrict__ Wm, const float* __restrict__ Hin,
                     float* __restrict__ part, int Kld, int Ki)
{
    extern __shared__ float smem[];
    float* sw = smem;                 // [2][KC][WST]  sw[i][o]
    float* sh = smem + 2 * SW_SZ;     // [2][KC][HST]  sh[i][b]

    const int tid = threadIdx.x;
    const int o0  = blockIdx.x * OT;
    const int b0  = blockIdx.y * BT;
    const int i0  = blockIdx.z * Ki;

    const int og = tid & 31;   // compute: o = o0 + og*4 + oo
    const int bg = tid >> 5;   // compute: b = b0 + bg*8 + bb
    const int lo = tid & 7;    // loader: i4 slot
    const int ro = tid >> 3;   // loader: row slot (0..31)

    const float init = (MODE == M_FMA) ? 0.0f
                     : (MODE == M_MAX) ? -3.402823466e38f : 3.402823466e38f;
    float acc[8][4];
#pragma unroll
    for (int bb = 0; bb < 8; bb++)
#pragma unroll
        for (int oo = 0; oo < 4; oo++) acc[bb][oo] = init;

    const float* wb = Wm  + (o0 + ro) * Kld + i0 + lo * 4;  // rows ro,+32,+64,+96
    const float* hb = Hin + (b0 + ro) * Kld + i0 + lo * 4;  // rows ro,+32

    float4 wreg[4], hreg[2];
    const int nC = Ki / KC;

    // ---- prologue: chunk 0 -> regs -> buf 0 ----
#pragma unroll
    for (int r = 0; r < 4; r++) wreg[r] = *(const float4*)(wb + r * 32 * Kld);
#pragma unroll
    for (int rr = 0; rr < 2; rr++) hreg[rr] = *(const float4*)(hb + rr * 32 * Kld);
    {
#pragma unroll
        for (int r = 0; r < 4; r++) {
            const int col = r * 32 + ro;
            sw[(lo * 4 + 0) * WST + col] = wreg[r].x;
            sw[(lo * 4 + 1) * WST + col] = wreg[r].y;
            sw[(lo * 4 + 2) * WST + col] = wreg[r].z;
            sw[(lo * 4 + 3) * WST + col] = wreg[r].w;
        }
#pragma unroll
        for (int rr = 0; rr < 2; rr++) {
            const int col = rr * 32 + ro;
            sh[(lo * 4 + 0) * HST + col] = hreg[rr].x;
            sh[(lo * 4 + 1) * HST + col] = hreg[rr].y;
            sh[(lo * 4 + 2) * HST + col] = hreg[rr].z;
            sh[(lo * 4 + 3) * HST + col] = hreg[rr].w;
        }
    }
    __syncthreads();

    for (int c = 0; c < nC; c++) {
        // prefetch chunk c+1 into regs (overlaps with compute)
        if (c + 1 < nC) {
            const int ic = (c + 1) * KC;
#pragma unroll
            for (int r = 0; r < 4; r++)
                wreg[r] = *(const float4*)(wb + r * 32 * Kld + ic);
#pragma unroll
            for (int rr = 0; rr < 2; rr++)
                hreg[rr] = *(const float4*)(hb + rr * 32 * Kld + ic);
        }

        const float* pw = sw + (c & 1) * SW_SZ;
        const float* ph = sh + (c & 1) * SH_SZ;
#pragma unroll 4
        for (int i = 0; i < KC; i++) {
            const float4 wv = *(const float4*)&pw[i * WST + og * 4];      // conflict-free
            const float4 h0 = *(const float4*)&ph[i * HST + bg * 8];      // broadcast
            const float4 h1 = *(const float4*)&ph[i * HST + bg * 8 + 4];  // broadcast
            // direct float4 component use — no register staging arrays
#define SR_UPD(bb, hv)                                   \
            acc[bb][0] = red<MODE>(acc[bb][0], wv.x, hv); \
            acc[bb][1] = red<MODE>(acc[bb][1], wv.y, hv); \
            acc[bb][2] = red<MODE>(acc[bb][2], wv.z, hv); \
            acc[bb][3] = red<MODE>(acc[bb][3], wv.w, hv);
            SR_UPD(0, h0.x)  SR_UPD(1, h0.y)  SR_UPD(2, h0.z)  SR_UPD(3, h0.w)
            SR_UPD(4, h1.x)  SR_UPD(5, h1.y)  SR_UPD(6, h1.z)  SR_UPD(7, h1.w)
#undef SR_UPD
        }

        // stage chunk c+1 into the other buffer; single barrier per chunk
        if (c + 1 < nC) {
            float* qw = sw + ((c + 1) & 1) * SW_SZ;
            float* qh = sh + ((c + 1) & 1) * SH_SZ;
#pragma unroll
            for (int r = 0; r < 4; r++) {
                const int col = r * 32 + ro;
                qw[(lo * 4 + 0) * WST + col] = wreg[r].x;
                qw[(lo * 4 + 1) * WST + col] = wreg[r].y;
                qw[(lo * 4 + 2) * WST + col] = wreg[r].z;
                qw[(lo * 4 + 3) * WST + col] = wreg[r].w;
            }
#pragma unroll
            for (int rr = 0; rr < 2; rr++) {
                const int col = rr * 32 + ro;
                qh[(lo * 4 + 0) * HST + col] = hreg[rr].x;
                qh[(lo * 4 + 1) * HST + col] = hreg[rr].y;
                qh[(lo * 4 + 2) * HST + col] = hreg[rr].z;
                qh[(lo * 4 + 3) * HST + col] = hreg[rr].w;
            }
            __syncthreads();
        }
    }

    float* pout = part + (blockIdx.z * NB + b0 + bg * 8) * HD + o0 + og * 4;
#pragma unroll
    for (int bb = 0; bb < 8; bb++)
        *(float4*)(pout + bb * HD) =
            make_float4(acc[bb][0], acc[bb][1], acc[bb][2], acc[bb][3]);
}

// Reduce SPLIT partials -> dense activation. TWO threads per output float4
// (each reduces SPLIT/2 slices, MLP=4), neighbor-lane shfl merge.
// base splits one combine across launches (keeps semiring at capture idx 3).
template<int MODE>
__global__ __launch_bounds__(256)
void combine_kernel(const float* __restrict__ part, float* __restrict__ out,
                    const float* __restrict__ bias, int base)
{
    const int gid  = base + blockIdx.x * 256 + threadIdx.x;
    const int idx  = gid >> 1;                        // output float4 index
    const int half = gid & 1;                         // slice group
    const float4* p = (const float4*)part + idx + half * (SPLIT / 2) * (NB * HD / 4);

    float4 v = p[0];
#pragma unroll
    for (int s = 1; s < SPLIT / 2; s++) {
        const float4 u = p[s * (NB * HD / 4)];
        if (MODE == M_FMA) {
            v.x += u.x; v.y += u.y; v.z += u.z; v.w += u.w;
        } else if (MODE == M_MAX) {
            v.x = fmaxf(v.x, u.x); v.y = fmaxf(v.y, u.y);
            v.z = fmaxf(v.z, u.z); v.w = fmaxf(v.w, u.w);
        } else {
            v.x = fminf(v.x, u.x); v.y = fminf(v.y, u.y);
            v.z = fminf(v.z, u.z); v.w = fminf(v.w, u.w);
        }
    }
    float4 w;
    w.x = __shfl_xor_sync(0xffffffffu, v.x, 1);
    w.y = __shfl_xor_sync(0xffffffffu, v.y, 1);
    w.z = __shfl_xor_sync(0xffffffffu, v.z, 1);
    w.w = __shfl_xor_sync(0xffffffffu, v.w, 1);
    if (MODE == M_FMA) {
        v.x += w.x; v.y += w.y; v.z += w.z; v.w += w.w;
    } else if (MODE == M_MAX) {
        v.x = fmaxf(v.x, w.x); v.y = fmaxf(v.y, w.y);
        v.z = fmaxf(v.z, w.z); v.w = fmaxf(v.w, w.w);
    } else {
        v.x = fminf(v.x, w.x); v.y = fminf(v.y, w.y);
        v.z = fminf(v.z, w.z); v.w = fminf(v.w, w.w);
    }

    if (half == 0) {
        if (MODE == M_FMA) {
            const float4 b = *(const float4*)(bias + (idx & (HD / 4 - 1)) * 4);
            v.x += b.x; v.y += b.y; v.z += b.z; v.w += b.w;
        }
        ((float4*)out)[idx] = v;
    }
}

// One CTA per batch row b: stage dense h3 row into smem, 8 warps x 18 dots.
__global__ __launch_bounds__(256)
void fcout_kernel(const float* __restrict__ h3, const float* __restrict__ Wout,
                  const float* __restrict__ bout, float* __restrict__ q)
{
    __shared__ float sh[HD];
    const int b    = blockIdx.x;
    const int tid  = threadIdx.x;
    const int wid  = tid >> 5;
    const int lane = tid & 31;

    ((float4*)sh)[tid] = ((const float4*)h3)[b * (HD / 4) + tid];
    __syncthreads();

    for (int a = wid; a < NA; a += 8) {
        const float4* wr = (const float4*)(Wout + a * HD);
        const float4* hs = (const float4*)sh;
        float s = 0.0f;
#pragma unroll
        for (int k = 0; k < HD / 128; k++) {
            const float4 w4 = wr[lane + k * 32];
            const float4 h4 = hs[lane + k * 32];
            s = fmaf(w4.x, h4.x, s);
            s = fmaf(w4.y, h4.y, s);
            s = fmaf(w4.z, h4.z, s);
            s = fmaf(w4.w, h4.w, s);
        }
#pragma unroll
        for (int d = 16; d; d >>= 1) s += __shfl_xor_sync(0xffffffffu, s, d);
        if (lane == 0) q[b * NA + a] = s + bout[a];
    }
}

extern "C" void kernel_launch(void* const* d_in, const int* in_sizes, int n_in,
                              void* d_out, int out_size)
{
    const float* x     = (const float*)d_in[0];
    const float* W_in  = (const float*)d_in[1];
    const float* b_in  = (const float*)d_in[2];
    const float* W_max = (const float*)d_in[3];
    const float* W_min = (const float*)d_in[4];
    const float* W_out = (const float*)d_in[5];
    const float* b_out = (const float*)d_in[6];
    float* q = (float*)d_out;

    float *part, *h1, *h2, *h3;
    cudaGetSymbolAddress((void**)&part, g_part);
    cudaGetSymbolAddress((void**)&h1, g_h1);
    cudaGetSymbolAddress((void**)&h2, g_h2);
    cudaGetSymbolAddress((void**)&h3, g_h3);

    cudaFuncSetAttribute(semiring_kernel<M_FMA>,
                         cudaFuncAttributeMaxDynamicSharedMemorySize, SMEM_BYTES);
    cudaFuncSetAttribute(semiring_kernel<M_MAX>,
                         cudaFuncAttributeMaxDynamicSharedMemorySize, SMEM_BYTES);
    cudaFuncSetAttribute(semiring_kernel<M_MIN>,
                         cudaFuncAttributeMaxDynamicSharedMemorySize, SMEM_BYTES);

    const dim3 grid(HD / OT, NB / BT, SPLIT);   // (8, 4, 8) = 256 CTAs, 2/SM
    const int  G2 = NB * HD / 4 * 2;            // combine thread count (131072)

    // 0) fc_in partials
    semiring_kernel<M_FMA><<<grid, NT, SMEM_BYTES>>>(W_in, x, part, NOBS, NOBS / SPLIT);
    // 1,2) combine(sum,+b_in) -> h1, split so launch #3 is a semiring
    combine_kernel<M_FMA><<<G2 / 2 / 256, 256>>>(part, h1, b_in, 0);
    combine_kernel<M_FMA><<<G2 / 2 / 256, 256>>>(part, h1, b_in, G2 / 2);

    // 3) max-plus partials  (ncu capture lands HERE)
    semiring_kernel<M_MAX><<<grid, NT, SMEM_BYTES>>>(W_max, h1, part, HD, HD / SPLIT);
    // 4) combine(max) -> h2
    combine_kernel<M_MAX><<<G2 / 256, 256>>>(part, h2, nullptr, 0);

    // 5) min-plus partials
    semiring_kernel<M_MIN><<<grid, NT, SMEM_BYTES>>>(W_min, h2, part, HD, HD / SPLIT);
    // 6) combine(min) -> h3
    combine_kernel<M_MIN><<<G2 / 256, 256>>>(part, h3, nullptr, 0);

    // 7) fc_out
    fcout_kernel<<<NB, 256>>>(h3, W_out, b_out, q);
}